// round 3
// baseline (speedup 1.0000x reference)
#include <cuda_runtime.h>
#include <math.h>

#define N_ROWS 4096
#define V_DIM  204
#define H_DIM  128
#define TN     128
#define GROUPS 9
#define VPG    23
#define NH     (N_ROWS * H_DIM)

// Deterministic partial-sum scratch (one slab per v-group). 18.9 MB static.
__device__ float g_part[GROUPS * N_ROWS * H_DIM];

__device__ __forceinline__ float sigmoidf_(float z) { return 1.0f / (1.0f + expf(-z)); }
__device__ __forceinline__ float eluf_(float z)     { return z > 0.0f ? z : expm1f(z); }

// ---------------------------------------------------------------------------
// Kernel W: weight network -> wts[n, v] (written into the wts half of d_out)
//   a  = elu(xs @ wfc1_w + wfc1_b)          (N,204)@(204,128)
//   a2 = a @ wfc2_w + wfc2_b                (N,128)@(128,128)
//   g  = a2 @ wglu_w + wglu_b               (N,128)@(128,408)
//   hg = g[:, :204] * sigmoid(g[:, 204:])
//   wts = softmax(LN(xs + hg; wln_g, wln_b), axis=-1)
// One CTA = 8 rows, 128 threads.
// ---------------------------------------------------------------------------
__global__ __launch_bounds__(128) void kW(
    const float* __restrict__ x,
    const float* __restrict__ wfc1_w, const float* __restrict__ wfc1_b,
    const float* __restrict__ wfc2_w, const float* __restrict__ wfc2_b,
    const float* __restrict__ wglu_w, const float* __restrict__ wglu_b,
    const float* __restrict__ wln_g,  const float* __restrict__ wln_b,
    float* __restrict__ wts_out)
{
    __shared__ float xs_s[8][208];
    __shared__ float a_s[8][128];
    __shared__ float a2_s[8][128];
    __shared__ float g_s[8][416];

    const int tid = threadIdx.x;
    const int n0  = blockIdx.x * 8;

    for (int idx = tid; idx < 8 * V_DIM; idx += 128) {
        int r = idx / V_DIM, v = idx - r * V_DIM;
        xs_s[r][v] = x[(n0 + r) * V_DIM + v];
    }
    __syncthreads();

    // layer 1: elu(xs @ wfc1 + b), output col = tid
    {
        float acc[8];
        #pragma unroll
        for (int r = 0; r < 8; r++) acc[r] = 0.0f;
        for (int k = 0; k < V_DIM; k++) {
            float w = wfc1_w[k * 128 + tid];
            #pragma unroll
            for (int r = 0; r < 8; r++) acc[r] = fmaf(xs_s[r][k], w, acc[r]);
        }
        float b = wfc1_b[tid];
        #pragma unroll
        for (int r = 0; r < 8; r++) a_s[r][tid] = eluf_(acc[r] + b);
    }
    __syncthreads();

    // layer 2: a @ wfc2 + b
    {
        float acc[8];
        #pragma unroll
        for (int r = 0; r < 8; r++) acc[r] = 0.0f;
        for (int k = 0; k < 128; k++) {
            float w = wfc2_w[k * 128 + tid];
            #pragma unroll
            for (int r = 0; r < 8; r++) acc[r] = fmaf(a_s[r][k], w, acc[r]);
        }
        float b = wfc2_b[tid];
        #pragma unroll
        for (int r = 0; r < 8; r++) a2_s[r][tid] = acc[r] + b;
    }
    __syncthreads();

    // glu layer: a2 @ wglu + b, 408 cols
    for (int jj = tid; jj < 2 * V_DIM; jj += 128) {
        float acc[8];
        #pragma unroll
        for (int r = 0; r < 8; r++) acc[r] = 0.0f;
        for (int k = 0; k < 128; k++) {
            float w = wglu_w[k * (2 * V_DIM) + jj];
            #pragma unroll
            for (int r = 0; r < 8; r++) acc[r] = fmaf(a2_s[r][k], w, acc[r]);
        }
        float b = wglu_b[jj];
        #pragma unroll
        for (int r = 0; r < 8; r++) g_s[r][jj] = acc[r] + b;
    }
    __syncthreads();

    // per-row GLU + LN + softmax, one warp per 2 rows
    const int warp = tid >> 5, lane = tid & 31;
    for (int r = warp * 2; r < warp * 2 + 2; r++) {
        float s1 = 0.0f, s2 = 0.0f;
        for (int v = lane; v < V_DIM; v += 32) {
            float z = xs_s[r][v] + g_s[r][v] * sigmoidf_(g_s[r][V_DIM + v]);
            g_s[r][v] = z;
            s1 += z; s2 += z * z;
        }
        #pragma unroll
        for (int m = 16; m; m >>= 1) {
            s1 += __shfl_xor_sync(0xffffffffu, s1, m);
            s2 += __shfl_xor_sync(0xffffffffu, s2, m);
        }
        float mu  = s1 * (1.0f / (float)V_DIM);
        float var = s2 * (1.0f / (float)V_DIM) - mu * mu;
        float rs  = rsqrtf(var + 1e-5f);

        float mx = -3.4e38f;
        for (int v = lane; v < V_DIM; v += 32) {
            float y = fmaf((g_s[r][v] - mu) * rs, wln_g[v], wln_b[v]);
            g_s[r][v] = y;
            mx = fmaxf(mx, y);
        }
        #pragma unroll
        for (int m = 16; m; m >>= 1) mx = fmaxf(mx, __shfl_xor_sync(0xffffffffu, mx, m));

        float se = 0.0f;
        for (int v = lane; v < V_DIM; v += 32) {
            float e = expf(g_s[r][v] - mx);
            g_s[r][v] = e;
            se += e;
        }
        #pragma unroll
        for (int m = 16; m; m >>= 1) se += __shfl_xor_sync(0xffffffffu, se, m);
        float inv = 1.0f / se;
        for (int v = lane; v < V_DIM; v += 32)
            wts_out[(n0 + r) * V_DIM + v] = g_s[r][v] * inv;
    }
}

// ---------------------------------------------------------------------------
// Kernel V helpers
// ---------------------------------------------------------------------------
__device__ __forceinline__ void gemm_128(float c[8][8], const float* __restrict__ aT,
                                         const float* __restrict__ bS, int tx, int ty)
{
    #pragma unroll 2
    for (int k = 0; k < 128; k++) {
        float4 a0 = *(const float4*)(aT + k * 128 + ty * 8);
        float4 a1 = *(const float4*)(aT + k * 128 + ty * 8 + 4);
        float4 b0 = *(const float4*)(bS + k * 128 + tx * 8);
        float4 b1 = *(const float4*)(bS + k * 128 + tx * 8 + 4);
        float av[8] = {a0.x, a0.y, a0.z, a0.w, a1.x, a1.y, a1.z, a1.w};
        float bv[8] = {b0.x, b0.y, b0.z, b0.w, b1.x, b1.y, b1.z, b1.w};
        #pragma unroll
        for (int i = 0; i < 8; i++)
            #pragma unroll
            for (int j = 0; j < 8; j++)
                c[i][j] = fmaf(av[i], bv[j], c[i][j]);
    }
}

// stage glu_w half (128 g x 128 k, row-major g) transposed into wS[k][g]
__device__ __forceinline__ void load_gluT(float* __restrict__ wS,
                                          const float* __restrict__ gbase, int tid)
{
    #pragma unroll
    for (int r = 0; r < 16; r++) {
        int m  = tid + 256 * r;     // 0..4095
        int g  = m & 127;
        int kq = m >> 7;            // 0..31
        float4 val = *(const float4*)(gbase + g * 128 + kq * 4);
        wS[(kq * 4 + 0) * 128 + g] = val.x;
        wS[(kq * 4 + 1) * 128 + g] = val.y;
        wS[(kq * 4 + 2) * 128 + g] = val.z;
        wS[(kq * 4 + 3) * 128 + g] = val.w;
    }
}

// ---------------------------------------------------------------------------
// Kernel V: per-variable GRN fused with weighted accumulation.
// Grid (32 n-tiles, 9 v-groups). 256 threads, 8x8 microtiles.
// ---------------------------------------------------------------------------
__global__ __launch_bounds__(256, 1) void kV(
    const float* __restrict__ x,
    const float* __restrict__ fc1_w,  const float* __restrict__ fc1_b,
    const float* __restrict__ fc2_w,  const float* __restrict__ fc2_b,
    const float* __restrict__ glu_w,  const float* __restrict__ glu_b,
    const float* __restrict__ skip_w, const float* __restrict__ skip_b,
    const float* __restrict__ ln_g,   const float* __restrict__ ln_b,
    const float* __restrict__ wts)
{
    extern __shared__ float sm[];
    float* hT  = sm;            // 128x128: h (transposed), later h2 (transposed)
    float* wS  = sm + 16384;    // 128x128: staged weight operand
    float* gaS = sm + 32768;    // 128x128: fc_out half of GLU, later LN scratch
    __shared__ float x_s[128], w1_s[128], b1_s[128], skw_s[128], skb_s[128], wts_s[128];

    const int tid = threadIdx.x;
    const int tx  = tid & 15;
    const int ty  = tid >> 4;
    const int n0  = blockIdx.x * TN;
    const int v0  = blockIdx.y * VPG;
    const int v1  = (v0 + VPG < V_DIM) ? (v0 + VPG) : V_DIM;

    float lng[8], lnb[8];
    #pragma unroll
    for (int j = 0; j < 8; j++) { lng[j] = ln_g[tx * 8 + j]; lnb[j] = ln_b[tx * 8 + j]; }

    float oacc[8][8];
    #pragma unroll
    for (int i = 0; i < 8; i++)
        #pragma unroll
        for (int j = 0; j < 8; j++) oacc[i][j] = 0.0f;

    for (int v = v0; v < v1; v++) {
        __syncthreads();  // previous iteration fully done with smem

        if (tid < 128) {
            x_s[tid]   = x[(n0 + tid) * V_DIM + v];
            w1_s[tid]  = fc1_w[v * H_DIM + tid];
            b1_s[tid]  = fc1_b[v * H_DIM + tid];
            skw_s[tid] = skip_w[v * H_DIM + tid];
            skb_s[tid] = skip_b[v * H_DIM + tid];
            wts_s[tid] = wts[(n0 + tid) * V_DIM + v];
        }
        // stage fc2_w[v] (already K-major: [h][k_out])
        {
            const float4* src = (const float4*)(fc2_w + (size_t)v * 16384);
            float4* dst = (float4*)wS;
            #pragma unroll
            for (int i = 0; i < 16; i++) dst[tid + 256 * i] = src[tid + 256 * i];
        }
        __syncthreads();

        // h[n][h'] = elu(x[n,v]*fc1_w[v,h'] + fc1_b[v,h']) stored transposed hT[h'][n]
        #pragma unroll
        for (int i = 0; i < 8; i++) {
            float xi = x_s[ty * 8 + i];
            #pragma unroll
            for (int j = 0; j < 8; j++) {
                int jj = tx * 8 + j;
                float z = fmaf(xi, w1_s[jj], b1_s[jj]);
                hT[jj * 128 + ty * 8 + i] = (z > 0.0f) ? z : expm1f(z);
            }
        }
        __syncthreads();

        float c[8][8];
        #pragma unroll
        for (int i = 0; i < 8; i++)
            #pragma unroll
            for (int j = 0; j < 8; j++) c[i][j] = 0.0f;
        gemm_128(c, hT, wS, tx, ty);                 // h2 = h @ fc2_w[v]
        __syncthreads();

        // store h2 (with bias) transposed back into hT; stage glu half 0
        #pragma unroll
        for (int j = 0; j < 8; j++) {
            int jj = tx * 8 + j;
            float b = fc2_b[v * 128 + jj];
            #pragma unroll
            for (int i = 0; i < 8; i++)
                hT[jj * 128 + ty * 8 + i] = c[i][j] + b;
        }
        load_gluT(wS, glu_w + (size_t)v * 32768, tid);
        __syncthreads();

        #pragma unroll
        for (int i = 0; i < 8; i++)
            #pragma unroll
            for (int j = 0; j < 8; j++) c[i][j] = 0.0f;
        gemm_128(c, hT, wS, tx, ty);                 // fc_out half of GLU
        #pragma unroll
        for (int i = 0; i < 8; i++)
            #pragma unroll
            for (int j = 0; j < 8; j++)
                gaS[(ty * 8 + i) * 128 + tx * 8 + j] = c[i][j] + glu_b[v * 256 + tx * 8 + j];
        __syncthreads();

        load_gluT(wS, glu_w + (size_t)v * 32768 + 16384, tid);
        __syncthreads();

        #pragma unroll
        for (int i = 0; i < 8; i++)
            #pragma unroll
            for (int j = 0; j < 8; j++) c[i][j] = 0.0f;
        gemm_128(c, hT, wS, tx, ty);                 // gate half of GLU

        // epilogue: GLU, skip, LayerNorm over H, weighted accumulate
        float gbb[8];
        #pragma unroll
        for (int j = 0; j < 8; j++) gbb[j] = glu_b[v * 256 + 128 + tx * 8 + j];

        #pragma unroll
        for (int i = 0; i < 8; i++) {
            int nl = ty * 8 + i;
            float xi = x_s[nl], wt = wts_s[nl];
            float s1 = 0.0f, s2 = 0.0f;
            #pragma unroll
            for (int j = 0; j < 8; j++) {
                int jj = tx * 8 + j;
                float gb  = c[i][j] + gbb[j];
                float val = gaS[nl * 128 + jj] * sigmoidf_(gb)
                          + fmaf(xi, skw_s[jj], skb_s[jj]);
                gaS[nl * 128 + jj] = val;   // own slot: no sync needed
                s1 += val; s2 += val * val;
            }
            #pragma unroll
            for (int m = 8; m; m >>= 1) {
                s1 += __shfl_xor_sync(0xffffffffu, s1, m);
                s2 += __shfl_xor_sync(0xffffffffu, s2, m);
            }
            float mu = s1 * (1.0f / 128.0f);
            float rs = rsqrtf(s2 * (1.0f / 128.0f) - mu * mu + 1e-5f);
            #pragma unroll
            for (int j = 0; j < 8; j++) {
                float vn = (gaS[nl * 128 + tx * 8 + j] - mu) * rs;
                oacc[i][j] = fmaf(wt, fmaf(vn, lng[j], lnb[j]), oacc[i][j]);
            }
        }
    }

    // write deterministic partial for this (group, n-tile)
    float* pp = g_part + ((size_t)blockIdx.y * N_ROWS + n0) * H_DIM;
    #pragma unroll
    for (int i = 0; i < 8; i++) {
        float4 w0 = make_float4(oacc[i][0], oacc[i][1], oacc[i][2], oacc[i][3]);
        float4 w1 = make_float4(oacc[i][4], oacc[i][5], oacc[i][6], oacc[i][7]);
        *(float4*)(pp + (ty * 8 + i) * 128 + tx * 8)     = w0;
        *(float4*)(pp + (ty * 8 + i) * 128 + tx * 8 + 4) = w1;
    }
}

// ---------------------------------------------------------------------------
// Kernel R: fixed-order reduction of the 9 group partials -> out
// ---------------------------------------------------------------------------
__global__ __launch_bounds__(256) void kR(float* __restrict__ out)
{
    int idx = blockIdx.x * 256 + threadIdx.x;
    float s = 0.0f;
    #pragma unroll
    for (int g = 0; g < GROUPS; g++) s += g_part[(size_t)g * NH + idx];
    out[idx] = s;
}

// ---------------------------------------------------------------------------
extern "C" void kernel_launch(void* const* d_in, const int* in_sizes, int n_in,
                              void* d_out, int out_size)
{
    const float* x      = (const float*)d_in[0];
    const float* fc1_w  = (const float*)d_in[1];
    const float* fc1_b  = (const float*)d_in[2];
    const float* fc2_w  = (const float*)d_in[3];
    const float* fc2_b  = (const float*)d_in[4];
    const float* glu_w  = (const float*)d_in[5];
    const float* glu_b  = (const float*)d_in[6];
    const float* skip_w = (const float*)d_in[7];
    const float* skip_b = (const float*)d_in[8];
    const float* ln_g   = (const float*)d_in[9];
    const float* ln_b   = (const float*)d_in[10];
    const float* wfc1_w = (const float*)d_in[11];
    const float* wfc1_b = (const float*)d_in[12];
    const float* wfc2_w = (const float*)d_in[13];
    const float* wfc2_b = (const float*)d_in[14];
    const float* wglu_w = (const float*)d_in[15];
    const float* wglu_b = (const float*)d_in[16];
    const float* wln_g  = (const float*)d_in[17];
    const float* wln_b  = (const float*)d_in[18];

    float* out = (float*)d_out;
    float* wts = out + NH;   // tuple (out, wts) flattened: out first, then wts

    cudaFuncSetAttribute(kV, cudaFuncAttributeMaxDynamicSharedMemorySize, 196608);

    kW<<<N_ROWS / 8, 128>>>(x, wfc1_w, wfc1_b, wfc2_w, wfc2_b,
                            wglu_w, wglu_b, wln_g, wln_b, wts);
    kV<<<dim3(N_ROWS / TN, GROUPS), 256, 196608>>>(
        x, fc1_w, fc1_b, fc2_w, fc2_b, glu_w, glu_b,
        skip_w, skip_b, ln_g, ln_b, wts);
    kR<<<NH / 256, 256>>>(out);
}

// round 4
// speedup vs baseline: 5.4497x; 5.4497x over previous
#include <cuda_runtime.h>
#include <math.h>

#define N_ROWS 4096
#define V_DIM  204
#define H_DIM  128
#define NH     (N_ROWS * H_DIM)

// interpolation table: F_v(x) sampled at J_NODES uniform nodes over [XMIN, XMAX]
#define J_NODES 512
#define XMIN    (-6.5f)
#define XMAX    ( 6.5f)

// 204 * 512 * 128 floats = 53.5 MB (L2-resident)
__device__ float g_tab[(size_t)V_DIM * J_NODES * H_DIM];

__device__ __forceinline__ float sigmoidf_(float z) { return 1.0f / (1.0f + expf(-z)); }
__device__ __forceinline__ float eluf_(float z)     { return z > 0.0f ? z : expm1f(z); }

// ---------------------------------------------------------------------------
// Kernel W: weight network -> wts[n, v]  (unchanged from R3, exact fp32)
// ---------------------------------------------------------------------------
__global__ __launch_bounds__(128) void kW(
    const float* __restrict__ x,
    const float* __restrict__ wfc1_w, const float* __restrict__ wfc1_b,
    const float* __restrict__ wfc2_w, const float* __restrict__ wfc2_b,
    const float* __restrict__ wglu_w, const float* __restrict__ wglu_b,
    const float* __restrict__ wln_g,  const float* __restrict__ wln_b,
    float* __restrict__ wts_out)
{
    __shared__ float xs_s[8][208];
    __shared__ float a_s[8][128];
    __shared__ float a2_s[8][128];
    __shared__ float g_s[8][416];

    const int tid = threadIdx.x;
    const int n0  = blockIdx.x * 8;

    for (int idx = tid; idx < 8 * V_DIM; idx += 128) {
        int r = idx / V_DIM, v = idx - r * V_DIM;
        xs_s[r][v] = x[(n0 + r) * V_DIM + v];
    }
    __syncthreads();

    {
        float acc[8];
        #pragma unroll
        for (int r = 0; r < 8; r++) acc[r] = 0.0f;
        for (int k = 0; k < V_DIM; k++) {
            float w = wfc1_w[k * 128 + tid];
            #pragma unroll
            for (int r = 0; r < 8; r++) acc[r] = fmaf(xs_s[r][k], w, acc[r]);
        }
        float b = wfc1_b[tid];
        #pragma unroll
        for (int r = 0; r < 8; r++) a_s[r][tid] = eluf_(acc[r] + b);
    }
    __syncthreads();

    {
        float acc[8];
        #pragma unroll
        for (int r = 0; r < 8; r++) acc[r] = 0.0f;
        for (int k = 0; k < 128; k++) {
            float w = wfc2_w[k * 128 + tid];
            #pragma unroll
            for (int r = 0; r < 8; r++) acc[r] = fmaf(a_s[r][k], w, acc[r]);
        }
        float b = wfc2_b[tid];
        #pragma unroll
        for (int r = 0; r < 8; r++) a2_s[r][tid] = acc[r] + b;
    }
    __syncthreads();

    for (int jj = tid; jj < 2 * V_DIM; jj += 128) {
        float acc[8];
        #pragma unroll
        for (int r = 0; r < 8; r++) acc[r] = 0.0f;
        for (int k = 0; k < 128; k++) {
            float w = wglu_w[k * (2 * V_DIM) + jj];
            #pragma unroll
            for (int r = 0; r < 8; r++) acc[r] = fmaf(a2_s[r][k], w, acc[r]);
        }
        float b = wglu_b[jj];
        #pragma unroll
        for (int r = 0; r < 8; r++) g_s[r][jj] = acc[r] + b;
    }
    __syncthreads();

    const int warp = tid >> 5, lane = tid & 31;
    for (int r = warp * 2; r < warp * 2 + 2; r++) {
        float s1 = 0.0f, s2 = 0.0f;
        for (int v = lane; v < V_DIM; v += 32) {
            float z = xs_s[r][v] + g_s[r][v] * sigmoidf_(g_s[r][V_DIM + v]);
            g_s[r][v] = z;
            s1 += z; s2 += z * z;
        }
        #pragma unroll
        for (int m = 16; m; m >>= 1) {
            s1 += __shfl_xor_sync(0xffffffffu, s1, m);
            s2 += __shfl_xor_sync(0xffffffffu, s2, m);
        }
        float mu  = s1 * (1.0f / (float)V_DIM);
        float var = s2 * (1.0f / (float)V_DIM) - mu * mu;
        float rs  = rsqrtf(var + 1e-5f);

        float mx = -3.4e38f;
        for (int v = lane; v < V_DIM; v += 32) {
            float y = fmaf((g_s[r][v] - mu) * rs, wln_g[v], wln_b[v]);
            g_s[r][v] = y;
            mx = fmaxf(mx, y);
        }
        #pragma unroll
        for (int m = 16; m; m >>= 1) mx = fmaxf(mx, __shfl_xor_sync(0xffffffffu, mx, m));

        float se = 0.0f;
        for (int v = lane; v < V_DIM; v += 32) {
            float e = expf(g_s[r][v] - mx);
            g_s[r][v] = e;
            se += e;
        }
        #pragma unroll
        for (int m = 16; m; m >>= 1) se += __shfl_xor_sync(0xffffffffu, se, m);
        float inv = 1.0f / se;
        for (int v = lane; v < V_DIM; v += 32)
            wts_out[(n0 + r) * V_DIM + v] = g_s[r][v] * inv;
    }
}

// ---------------------------------------------------------------------------
// GEMM helpers (unchanged)
// ---------------------------------------------------------------------------
__device__ __forceinline__ void gemm_128(float c[8][8], const float* __restrict__ aT,
                                         const float* __restrict__ bS, int tx, int ty)
{
    #pragma unroll 2
    for (int k = 0; k < 128; k++) {
        float4 a0 = *(const float4*)(aT + k * 128 + ty * 8);
        float4 a1 = *(const float4*)(aT + k * 128 + ty * 8 + 4);
        float4 b0 = *(const float4*)(bS + k * 128 + tx * 8);
        float4 b1 = *(const float4*)(bS + k * 128 + tx * 8 + 4);
        float av[8] = {a0.x, a0.y, a0.z, a0.w, a1.x, a1.y, a1.z, a1.w};
        float bv[8] = {b0.x, b0.y, b0.z, b0.w, b1.x, b1.y, b1.z, b1.w};
        #pragma unroll
        for (int i = 0; i < 8; i++)
            #pragma unroll
            for (int j = 0; j < 8; j++)
                c[i][j] = fmaf(av[i], bv[j], c[i][j]);
    }
}

__device__ __forceinline__ void load_gluT(float* __restrict__ wS,
                                          const float* __restrict__ gbase, int tid)
{
    #pragma unroll
    for (int r = 0; r < 16; r++) {
        int m  = tid + 256 * r;
        int g  = m & 127;
        int kq = m >> 7;
        float4 val = *(const float4*)(gbase + g * 128 + kq * 4);
        wS[(kq * 4 + 0) * 128 + g] = val.x;
        wS[(kq * 4 + 1) * 128 + g] = val.y;
        wS[(kq * 4 + 2) * 128 + g] = val.z;
        wS[(kq * 4 + 3) * 128 + g] = val.w;
    }
}

// ---------------------------------------------------------------------------
// Kernel T: build the table. One CTA per (v, 128-node tile).
// Identical math to the old kV body, with "rows" = interpolation nodes.
// ---------------------------------------------------------------------------
__global__ __launch_bounds__(256, 1) void kT(
    const float* __restrict__ fc1_w,  const float* __restrict__ fc1_b,
    const float* __restrict__ fc2_w,  const float* __restrict__ fc2_b,
    const float* __restrict__ glu_w,  const float* __restrict__ glu_b,
    const float* __restrict__ skip_w, const float* __restrict__ skip_b,
    const float* __restrict__ ln_g,   const float* __restrict__ ln_b)
{
    extern __shared__ float sm[];
    float* hT  = sm;            // 128x128
    float* wS  = sm + 16384;    // 128x128
    float* gaS = sm + 32768;    // 128x128
    __shared__ float x_s[128], w1_s[128], b1_s[128], skw_s[128], skb_s[128];

    const int tid = threadIdx.x;
    const int tx  = tid & 15;
    const int ty  = tid >> 4;
    const int v   = blockIdx.x;
    const int j0  = blockIdx.y * 128;
    const float dx = (XMAX - XMIN) / (float)(J_NODES - 1);

    float lng[8], lnb[8];
    #pragma unroll
    for (int j = 0; j < 8; j++) { lng[j] = ln_g[tx * 8 + j]; lnb[j] = ln_b[tx * 8 + j]; }

    if (tid < 128) {
        x_s[tid]   = XMIN + (float)(j0 + tid) * dx;
        w1_s[tid]  = fc1_w[v * H_DIM + tid];
        b1_s[tid]  = fc1_b[v * H_DIM + tid];
        skw_s[tid] = skip_w[v * H_DIM + tid];
        skb_s[tid] = skip_b[v * H_DIM + tid];
    }
    {   // stage fc2_w[v]
        const float4* src = (const float4*)(fc2_w + (size_t)v * 16384);
        float4* dst = (float4*)wS;
        #pragma unroll
        for (int i = 0; i < 16; i++) dst[tid + 256 * i] = src[tid + 256 * i];
    }
    __syncthreads();

    // h (transposed)
    #pragma unroll
    for (int i = 0; i < 8; i++) {
        float xi = x_s[ty * 8 + i];
        #pragma unroll
        for (int j = 0; j < 8; j++) {
            int jj = tx * 8 + j;
            float z = fmaf(xi, w1_s[jj], b1_s[jj]);
            hT[jj * 128 + ty * 8 + i] = (z > 0.0f) ? z : expm1f(z);
        }
    }
    __syncthreads();

    float c[8][8];
    #pragma unroll
    for (int i = 0; i < 8; i++)
        #pragma unroll
        for (int j = 0; j < 8; j++) c[i][j] = 0.0f;
    gemm_128(c, hT, wS, tx, ty);                 // h2 = h @ fc2_w[v]
    __syncthreads();

    #pragma unroll
    for (int j = 0; j < 8; j++) {
        int jj = tx * 8 + j;
        float b = fc2_b[v * 128 + jj];
        #pragma unroll
        for (int i = 0; i < 8; i++)
            hT[jj * 128 + ty * 8 + i] = c[i][j] + b;
    }
    load_gluT(wS, glu_w + (size_t)v * 32768, tid);
    __syncthreads();

    #pragma unroll
    for (int i = 0; i < 8; i++)
        #pragma unroll
        for (int j = 0; j < 8; j++) c[i][j] = 0.0f;
    gemm_128(c, hT, wS, tx, ty);                 // fc_out half
    #pragma unroll
    for (int i = 0; i < 8; i++)
        #pragma unroll
        for (int j = 0; j < 8; j++)
            gaS[(ty * 8 + i) * 128 + tx * 8 + j] = c[i][j] + glu_b[v * 256 + tx * 8 + j];
    __syncthreads();

    load_gluT(wS, glu_w + (size_t)v * 32768 + 16384, tid);
    __syncthreads();

    #pragma unroll
    for (int i = 0; i < 8; i++)
        #pragma unroll
        for (int j = 0; j < 8; j++) c[i][j] = 0.0f;
    gemm_128(c, hT, wS, tx, ty);                 // gate half

    float gbb[8];
    #pragma unroll
    for (int j = 0; j < 8; j++) gbb[j] = glu_b[v * 256 + 128 + tx * 8 + j];

    float* trow = g_tab + ((size_t)v * J_NODES + j0) * H_DIM;

    #pragma unroll
    for (int i = 0; i < 8; i++) {
        int nl = ty * 8 + i;
        float xi = x_s[nl];
        float s1 = 0.0f, s2 = 0.0f;
        #pragma unroll
        for (int j = 0; j < 8; j++) {
            int jj = tx * 8 + j;
            float gb  = c[i][j] + gbb[j];
            float val = gaS[nl * 128 + jj] * sigmoidf_(gb)
                      + fmaf(xi, skw_s[jj], skb_s[jj]);
            gaS[nl * 128 + jj] = val;
            s1 += val; s2 += val * val;
        }
        #pragma unroll
        for (int m = 8; m; m >>= 1) {
            s1 += __shfl_xor_sync(0xffffffffu, s1, m);
            s2 += __shfl_xor_sync(0xffffffffu, s2, m);
        }
        float mu = s1 * (1.0f / 128.0f);
        float rs = rsqrtf(s2 * (1.0f / 128.0f) - mu * mu + 1e-5f);
        float y[8];
        #pragma unroll
        for (int j = 0; j < 8; j++) {
            float vn = (gaS[nl * 128 + tx * 8 + j] - mu) * rs;
            y[j] = fmaf(vn, lng[j], lnb[j]);
        }
        *(float4*)(trow + (size_t)nl * 128 + tx * 8)     = make_float4(y[0], y[1], y[2], y[3]);
        *(float4*)(trow + (size_t)nl * 128 + tx * 8 + 4) = make_float4(y[4], y[5], y[6], y[7]);
    }
}

// ---------------------------------------------------------------------------
// Kernel I: cubic Lagrange interpolation + softmax-weighted accumulation.
// One warp per output row n. out[n,:] = sum_v sum_d wts[n,v]*c_d * T_v[j+d,:]
// ---------------------------------------------------------------------------
__global__ __launch_bounds__(256) void kI(
    const float* __restrict__ x,
    const float* __restrict__ wts,
    float* __restrict__ out)
{
    const int n    = blockIdx.x * 8 + (threadIdx.x >> 5);
    const int lane = threadIdx.x & 31;
    const float inv_dx = (float)(J_NODES - 1) / (XMAX - XMIN);
    const size_t base = (size_t)n * V_DIM;

    float4 acc = make_float4(0.0f, 0.0f, 0.0f, 0.0f);

    #pragma unroll 2
    for (int v = 0; v < V_DIM; v++) {
        float xv = __ldg(x + base + v);
        float wv = __ldg(wts + base + v);
        float t = (xv - XMIN) * inv_dx;
        int j = (int)t;
        j = max(1, min(j, J_NODES - 3));
        float f = t - (float)j;
        float fm1 = f - 1.0f, fm2 = f - 2.0f, fp1 = f + 1.0f;
        float c0 = wv * (-1.0f / 6.0f) * f * fm1 * fm2;
        float c1 = wv * 0.5f * fp1 * fm1 * fm2;
        float c2 = wv * (-0.5f) * fp1 * f * fm2;
        float c3 = wv * (1.0f / 6.0f) * fp1 * f * fm1;

        const float4* r = (const float4*)(g_tab + ((size_t)v * J_NODES + j - 1) * H_DIM) + lane;
        float4 t0 = __ldg(r);
        float4 t1 = __ldg(r + 32);
        float4 t2 = __ldg(r + 64);
        float4 t3 = __ldg(r + 96);

        acc.x = fmaf(c0, t0.x, fmaf(c1, t1.x, fmaf(c2, t2.x, fmaf(c3, t3.x, acc.x))));
        acc.y = fmaf(c0, t0.y, fmaf(c1, t1.y, fmaf(c2, t2.y, fmaf(c3, t3.y, acc.y))));
        acc.z = fmaf(c0, t0.z, fmaf(c1, t1.z, fmaf(c2, t2.z, fmaf(c3, t3.z, acc.z))));
        acc.w = fmaf(c0, t0.w, fmaf(c1, t1.w, fmaf(c2, t2.w, fmaf(c3, t3.w, acc.w))));
    }

    *(float4*)(out + (size_t)n * H_DIM + lane * 4) = acc;
}

// ---------------------------------------------------------------------------
extern "C" void kernel_launch(void* const* d_in, const int* in_sizes, int n_in,
                              void* d_out, int out_size)
{
    const float* x      = (const float*)d_in[0];
    const float* fc1_w  = (const float*)d_in[1];
    const float* fc1_b  = (const float*)d_in[2];
    const float* fc2_w  = (const float*)d_in[3];
    const float* fc2_b  = (const float*)d_in[4];
    const float* glu_w  = (const float*)d_in[5];
    const float* glu_b  = (const float*)d_in[6];
    const float* skip_w = (const float*)d_in[7];
    const float* skip_b = (const float*)d_in[8];
    const float* ln_g   = (const float*)d_in[9];
    const float* ln_b   = (const float*)d_in[10];
    const float* wfc1_w = (const float*)d_in[11];
    const float* wfc1_b = (const float*)d_in[12];
    const float* wfc2_w = (const float*)d_in[13];
    const float* wfc2_b = (const float*)d_in[14];
    const float* wglu_w = (const float*)d_in[15];
    const float* wglu_b = (const float*)d_in[16];
    const float* wln_g  = (const float*)d_in[17];
    const float* wln_b  = (const float*)d_in[18];

    float* out = (float*)d_out;
    float* wts = out + NH;   // tuple (out, wts): out first, then wts

    cudaFuncSetAttribute(kT, cudaFuncAttributeMaxDynamicSharedMemorySize, 196608);

    // table build first (independent of kW), then weights, then interpolation
    kT<<<dim3(V_DIM, J_NODES / 128), 256, 196608>>>(
        fc1_w, fc1_b, fc2_w, fc2_b, glu_w, glu_b,
        skip_w, skip_b, ln_g, ln_b);
    kW<<<N_ROWS / 8, 128>>>(x, wfc1_w, wfc1_b, wfc2_w, wfc2_b,
                            wglu_w, wglu_b, wln_g, wln_b, wts);
    kI<<<N_ROWS / 8, 256>>>(x, wts, out);
}

// round 5
// speedup vs baseline: 5.4739x; 1.0044x over previous
#include <cuda_runtime.h>
#include <math.h>

#define N_ROWS 4096
#define V_DIM  204
#define H_DIM  128
#define NH     (N_ROWS * H_DIM)

// interpolation table: F_v(x) sampled at J_NODES uniform nodes over [XMIN, XMAX]
#define J_NODES 512
#define XMIN    (-6.5f)
#define XMAX    ( 6.5f)

// 204 * 512 * 128 floats = 53.5 MB (L2-resident)
__device__ float g_tab[(size_t)V_DIM * J_NODES * H_DIM];

__device__ __forceinline__ float sigmoidf_(float z) { return 1.0f / (1.0f + expf(-z)); }
__device__ __forceinline__ float eluf_(float z)     { return z > 0.0f ? z : expm1f(z); }

// ---------------------------------------------------------------------------
// Kernel W: weight network -> wts[n, v]  (unchanged from R3, exact fp32)
// ---------------------------------------------------------------------------
__global__ __launch_bounds__(128) void kW(
    const float* __restrict__ x,
    const float* __restrict__ wfc1_w, const float* __restrict__ wfc1_b,
    const float* __restrict__ wfc2_w, const float* __restrict__ wfc2_b,
    const float* __restrict__ wglu_w, const float* __restrict__ wglu_b,
    const float* __restrict__ wln_g,  const float* __restrict__ wln_b,
    float* __restrict__ wts_out)
{
    __shared__ float xs_s[8][208];
    __shared__ float a_s[8][128];
    __shared__ float a2_s[8][128];
    __shared__ float g_s[8][416];

    const int tid = threadIdx.x;
    const int n0  = blockIdx.x * 8;

    for (int idx = tid; idx < 8 * V_DIM; idx += 128) {
        int r = idx / V_DIM, v = idx - r * V_DIM;
        xs_s[r][v] = x[(n0 + r) * V_DIM + v];
    }
    __syncthreads();

    {
        float acc[8];
        #pragma unroll
        for (int r = 0; r < 8; r++) acc[r] = 0.0f;
        for (int k = 0; k < V_DIM; k++) {
            float w = wfc1_w[k * 128 + tid];
            #pragma unroll
            for (int r = 0; r < 8; r++) acc[r] = fmaf(xs_s[r][k], w, acc[r]);
        }
        float b = wfc1_b[tid];
        #pragma unroll
        for (int r = 0; r < 8; r++) a_s[r][tid] = eluf_(acc[r] + b);
    }
    __syncthreads();

    {
        float acc[8];
        #pragma unroll
        for (int r = 0; r < 8; r++) acc[r] = 0.0f;
        for (int k = 0; k < 128; k++) {
            float w = wfc2_w[k * 128 + tid];
            #pragma unroll
            for (int r = 0; r < 8; r++) acc[r] = fmaf(a_s[r][k], w, acc[r]);
        }
        float b = wfc2_b[tid];
        #pragma unroll
        for (int r = 0; r < 8; r++) a2_s[r][tid] = acc[r] + b;
    }
    __syncthreads();

    for (int jj = tid; jj < 2 * V_DIM; jj += 128) {
        float acc[8];
        #pragma unroll
        for (int r = 0; r < 8; r++) acc[r] = 0.0f;
        for (int k = 0; k < 128; k++) {
            float w = wglu_w[k * (2 * V_DIM) + jj];
            #pragma unroll
            for (int r = 0; r < 8; r++) acc[r] = fmaf(a2_s[r][k], w, acc[r]);
        }
        float b = wglu_b[jj];
        #pragma unroll
        for (int r = 0; r < 8; r++) g_s[r][jj] = acc[r] + b;
    }
    __syncthreads();

    const int warp = tid >> 5, lane = tid & 31;
    for (int r = warp * 2; r < warp * 2 + 2; r++) {
        float s1 = 0.0f, s2 = 0.0f;
        for (int v = lane; v < V_DIM; v += 32) {
            float z = xs_s[r][v] + g_s[r][v] * sigmoidf_(g_s[r][V_DIM + v]);
            g_s[r][v] = z;
            s1 += z; s2 += z * z;
        }
        #pragma unroll
        for (int m = 16; m; m >>= 1) {
            s1 += __shfl_xor_sync(0xffffffffu, s1, m);
            s2 += __shfl_xor_sync(0xffffffffu, s2, m);
        }
        float mu  = s1 * (1.0f / (float)V_DIM);
        float var = s2 * (1.0f / (float)V_DIM) - mu * mu;
        float rs  = rsqrtf(var + 1e-5f);

        float mx = -3.4e38f;
        for (int v = lane; v < V_DIM; v += 32) {
            float y = fmaf((g_s[r][v] - mu) * rs, wln_g[v], wln_b[v]);
            g_s[r][v] = y;
            mx = fmaxf(mx, y);
        }
        #pragma unroll
        for (int m = 16; m; m >>= 1) mx = fmaxf(mx, __shfl_xor_sync(0xffffffffu, mx, m));

        float se = 0.0f;
        for (int v = lane; v < V_DIM; v += 32) {
            float e = expf(g_s[r][v] - mx);
            g_s[r][v] = e;
            se += e;
        }
        #pragma unroll
        for (int m = 16; m; m >>= 1) se += __shfl_xor_sync(0xffffffffu, se, m);
        float inv = 1.0f / se;
        for (int v = lane; v < V_DIM; v += 32)
            wts_out[(n0 + r) * V_DIM + v] = g_s[r][v] * inv;
    }
}

// ---------------------------------------------------------------------------
// GEMM helpers (unchanged)
// ---------------------------------------------------------------------------
__device__ __forceinline__ void gemm_128(float c[8][8], const float* __restrict__ aT,
                                         const float* __restrict__ bS, int tx, int ty)
{
    #pragma unroll 2
    for (int k = 0; k < 128; k++) {
        float4 a0 = *(const float4*)(aT + k * 128 + ty * 8);
        float4 a1 = *(const float4*)(aT + k * 128 + ty * 8 + 4);
        float4 b0 = *(const float4*)(bS + k * 128 + tx * 8);
        float4 b1 = *(const float4*)(bS + k * 128 + tx * 8 + 4);
        float av[8] = {a0.x, a0.y, a0.z, a0.w, a1.x, a1.y, a1.z, a1.w};
        float bv[8] = {b0.x, b0.y, b0.z, b0.w, b1.x, b1.y, b1.z, b1.w};
        #pragma unroll
        for (int i = 0; i < 8; i++)
            #pragma unroll
            for (int j = 0; j < 8; j++)
                c[i][j] = fmaf(av[i], bv[j], c[i][j]);
    }
}

__device__ __forceinline__ void load_gluT(float* __restrict__ wS,
                                          const float* __restrict__ gbase, int tid)
{
    #pragma unroll
    for (int r = 0; r < 16; r++) {
        int m  = tid + 256 * r;
        int g  = m & 127;
        int kq = m >> 7;
        float4 val = *(const float4*)(gbase + g * 128 + kq * 4);
        wS[(kq * 4 + 0) * 128 + g] = val.x;
        wS[(kq * 4 + 1) * 128 + g] = val.y;
        wS[(kq * 4 + 2) * 128 + g] = val.z;
        wS[(kq * 4 + 3) * 128 + g] = val.w;
    }
}

// ---------------------------------------------------------------------------
// Kernel T: build the table. One CTA per (v, 128-node tile).
// Identical math to the old kV body, with "rows" = interpolation nodes.
// ---------------------------------------------------------------------------
__global__ __launch_bounds__(256, 1) void kT(
    const float* __restrict__ fc1_w,  const float* __restrict__ fc1_b,
    const float* __restrict__ fc2_w,  const float* __restrict__ fc2_b,
    const float* __restrict__ glu_w,  const float* __restrict__ glu_b,
    const float* __restrict__ skip_w, const float* __restrict__ skip_b,
    const float* __restrict__ ln_g,   const float* __restrict__ ln_b)
{
    extern __shared__ float sm[];
    float* hT  = sm;            // 128x128
    float* wS  = sm + 16384;    // 128x128
    float* gaS = sm + 32768;    // 128x128
    __shared__ float x_s[128], w1_s[128], b1_s[128], skw_s[128], skb_s[128];

    const int tid = threadIdx.x;
    const int tx  = tid & 15;
    const int ty  = tid >> 4;
    const int v   = blockIdx.x;
    const int j0  = blockIdx.y * 128;
    const float dx = (XMAX - XMIN) / (float)(J_NODES - 1);

    float lng[8], lnb[8];
    #pragma unroll
    for (int j = 0; j < 8; j++) { lng[j] = ln_g[tx * 8 + j]; lnb[j] = ln_b[tx * 8 + j]; }

    if (tid < 128) {
        x_s[tid]   = XMIN + (float)(j0 + tid) * dx;
        w1_s[tid]  = fc1_w[v * H_DIM + tid];
        b1_s[tid]  = fc1_b[v * H_DIM + tid];
        skw_s[tid] = skip_w[v * H_DIM + tid];
        skb_s[tid] = skip_b[v * H_DIM + tid];
    }
    {   // stage fc2_w[v]
        const float4* src = (const float4*)(fc2_w + (size_t)v * 16384);
        float4* dst = (float4*)wS;
        #pragma unroll
        for (int i = 0; i < 16; i++) dst[tid + 256 * i] = src[tid + 256 * i];
    }
    __syncthreads();

    // h (transposed)
    #pragma unroll
    for (int i = 0; i < 8; i++) {
        float xi = x_s[ty * 8 + i];
        #pragma unroll
        for (int j = 0; j < 8; j++) {
            int jj = tx * 8 + j;
            float z = fmaf(xi, w1_s[jj], b1_s[jj]);
            hT[jj * 128 + ty * 8 + i] = (z > 0.0f) ? z : expm1f(z);
        }
    }
    __syncthreads();

    float c[8][8];
    #pragma unroll
    for (int i = 0; i < 8; i++)
        #pragma unroll
        for (int j = 0; j < 8; j++) c[i][j] = 0.0f;
    gemm_128(c, hT, wS, tx, ty);                 // h2 = h @ fc2_w[v]
    __syncthreads();

    #pragma unroll
    for (int j = 0; j < 8; j++) {
        int jj = tx * 8 + j;
        float b = fc2_b[v * 128 + jj];
        #pragma unroll
        for (int i = 0; i < 8; i++)
            hT[jj * 128 + ty * 8 + i] = c[i][j] + b;
    }
    load_gluT(wS, glu_w + (size_t)v * 32768, tid);
    __syncthreads();

    #pragma unroll
    for (int i = 0; i < 8; i++)
        #pragma unroll
        for (int j = 0; j < 8; j++) c[i][j] = 0.0f;
    gemm_128(c, hT, wS, tx, ty);                 // fc_out half
    #pragma unroll
    for (int i = 0; i < 8; i++)
        #pragma unroll
        for (int j = 0; j < 8; j++)
            gaS[(ty * 8 + i) * 128 + tx * 8 + j] = c[i][j] + glu_b[v * 256 + tx * 8 + j];
    __syncthreads();

    load_gluT(wS, glu_w + (size_t)v * 32768 + 16384, tid);
    __syncthreads();

    #pragma unroll
    for (int i = 0; i < 8; i++)
        #pragma unroll
        for (int j = 0; j < 8; j++) c[i][j] = 0.0f;
    gemm_128(c, hT, wS, tx, ty);                 // gate half

    float gbb[8];
    #pragma unroll
    for (int j = 0; j < 8; j++) gbb[j] = glu_b[v * 256 + 128 + tx * 8 + j];

    float* trow = g_tab + ((size_t)v * J_NODES + j0) * H_DIM;

    #pragma unroll
    for (int i = 0; i < 8; i++) {
        int nl = ty * 8 + i;
        float xi = x_s[nl];
        float s1 = 0.0f, s2 = 0.0f;
        #pragma unroll
        for (int j = 0; j < 8; j++) {
            int jj = tx * 8 + j;
            float gb  = c[i][j] + gbb[j];
            float val = gaS[nl * 128 + jj] * sigmoidf_(gb)
                      + fmaf(xi, skw_s[jj], skb_s[jj]);
            gaS[nl * 128 + jj] = val;
            s1 += val; s2 += val * val;
        }
        #pragma unroll
        for (int m = 8; m; m >>= 1) {
            s1 += __shfl_xor_sync(0xffffffffu, s1, m);
            s2 += __shfl_xor_sync(0xffffffffu, s2, m);
        }
        float mu = s1 * (1.0f / 128.0f);
        float rs = rsqrtf(s2 * (1.0f / 128.0f) - mu * mu + 1e-5f);
        float y[8];
        #pragma unroll
        for (int j = 0; j < 8; j++) {
            float vn = (gaS[nl * 128 + tx * 8 + j] - mu) * rs;
            y[j] = fmaf(vn, lng[j], lnb[j]);
        }
        *(float4*)(trow + (size_t)nl * 128 + tx * 8)     = make_float4(y[0], y[1], y[2], y[3]);
        *(float4*)(trow + (size_t)nl * 128 + tx * 8 + 4) = make_float4(y[4], y[5], y[6], y[7]);
    }
}

// ---------------------------------------------------------------------------
// Kernel I: cubic Lagrange interpolation + softmax-weighted accumulation.
// One warp per output row n. out[n,:] = sum_v sum_d wts[n,v]*c_d * T_v[j+d,:]
// ---------------------------------------------------------------------------
__global__ __launch_bounds__(256) void kI(
    const float* __restrict__ x,
    const float* __restrict__ wts,
    float* __restrict__ out)
{
    const int n    = blockIdx.x * 8 + (threadIdx.x >> 5);
    const int lane = threadIdx.x & 31;
    const float inv_dx = (float)(J_NODES - 1) / (XMAX - XMIN);
    const size_t base = (size_t)n * V_DIM;

    float4 acc = make_float4(0.0f, 0.0f, 0.0f, 0.0f);

    #pragma unroll 2
    for (int v = 0; v < V_DIM; v++) {
        float xv = __ldg(x + base + v);
        float wv = __ldg(wts + base + v);
        float t = (xv - XMIN) * inv_dx;
        int j = (int)t;
        j = max(1, min(j, J_NODES - 3));
        float f = t - (float)j;
        float fm1 = f - 1.0f, fm2 = f - 2.0f, fp1 = f + 1.0f;
        float c0 = wv * (-1.0f / 6.0f) * f * fm1 * fm2;
        float c1 = wv * 0.5f * fp1 * fm1 * fm2;
        float c2 = wv * (-0.5f) * fp1 * f * fm2;
        float c3 = wv * (1.0f / 6.0f) * fp1 * f * fm1;

        const float4* r = (const float4*)(g_tab + ((size_t)v * J_NODES + j - 1) * H_DIM) + lane;
        float4 t0 = __ldg(r);
        float4 t1 = __ldg(r + 32);
        float4 t2 = __ldg(r + 64);
        float4 t3 = __ldg(r + 96);

        acc.x = fmaf(c0, t0.x, fmaf(c1, t1.x, fmaf(c2, t2.x, fmaf(c3, t3.x, acc.x))));
        acc.y = fmaf(c0, t0.y, fmaf(c1, t1.y, fmaf(c2, t2.y, fmaf(c3, t3.y, acc.y))));
        acc.z = fmaf(c0, t0.z, fmaf(c1, t1.z, fmaf(c2, t2.z, fmaf(c3, t3.z, acc.z))));
        acc.w = fmaf(c0, t0.w, fmaf(c1, t1.w, fmaf(c2, t2.w, fmaf(c3, t3.w, acc.w))));
    }

    *(float4*)(out + (size_t)n * H_DIM + lane * 4) = acc;
}

// ---------------------------------------------------------------------------
extern "C" void kernel_launch(void* const* d_in, const int* in_sizes, int n_in,
                              void* d_out, int out_size)
{
    const float* x      = (const float*)d_in[0];
    const float* fc1_w  = (const float*)d_in[1];
    const float* fc1_b  = (const float*)d_in[2];
    const float* fc2_w  = (const float*)d_in[3];
    const float* fc2_b  = (const float*)d_in[4];
    const float* glu_w  = (const float*)d_in[5];
    const float* glu_b  = (const float*)d_in[6];
    const float* skip_w = (const float*)d_in[7];
    const float* skip_b = (const float*)d_in[8];
    const float* ln_g   = (const float*)d_in[9];
    const float* ln_b   = (const float*)d_in[10];
    const float* wfc1_w = (const float*)d_in[11];
    const float* wfc1_b = (const float*)d_in[12];
    const float* wfc2_w = (const float*)d_in[13];
    const float* wfc2_b = (const float*)d_in[14];
    const float* wglu_w = (const float*)d_in[15];
    const float* wglu_b = (const float*)d_in[16];
    const float* wln_g  = (const float*)d_in[17];
    const float* wln_b  = (const float*)d_in[18];

    float* out = (float*)d_out;
    float* wts = out + NH;   // tuple (out, wts): out first, then wts

    cudaFuncSetAttribute(kT, cudaFuncAttributeMaxDynamicSharedMemorySize, 196608);

    // table build first (independent of kW), then weights, then interpolation
    kT<<<dim3(V_DIM, J_NODES / 128), 256, 196608>>>(
        fc1_w, fc1_b, fc2_w, fc2_b, glu_w, glu_b,
        skip_w, skip_b, ln_g, ln_b);
    kW<<<N_ROWS / 8, 128>>>(x, wfc1_w, wfc1_b, wfc2_w, wfc2_b,
                            wglu_w, wglu_b, wln_g, wln_b, wts);
    kI<<<N_ROWS / 8, 256>>>(x, wts, out);
}

// round 6
// speedup vs baseline: 5.4746x; 1.0001x over previous
#include <cuda_runtime.h>
#include <math.h>

#define N_ROWS 4096
#define V_DIM  204
#define H_DIM  128
#define NH     (N_ROWS * H_DIM)

// interpolation table: F_v(x) sampled at J_NODES uniform nodes over [XMIN, XMAX]
#define J_NODES 512
#define XMIN    (-6.5f)
#define XMAX    ( 6.5f)

// 204 * 512 * 128 floats = 53.5 MB (L2-resident)
__device__ float g_tab[(size_t)V_DIM * J_NODES * H_DIM];

__device__ __forceinline__ float sigmoidf_(float z) { return 1.0f / (1.0f + expf(-z)); }
__device__ __forceinline__ float eluf_(float z)     { return z > 0.0f ? z : expm1f(z); }

// ---------------------------------------------------------------------------
// Kernel W: weight network -> wts[n, v]  (unchanged from R3, exact fp32)
// ---------------------------------------------------------------------------
__global__ __launch_bounds__(128) void kW(
    const float* __restrict__ x,
    const float* __restrict__ wfc1_w, const float* __restrict__ wfc1_b,
    const float* __restrict__ wfc2_w, const float* __restrict__ wfc2_b,
    const float* __restrict__ wglu_w, const float* __restrict__ wglu_b,
    const float* __restrict__ wln_g,  const float* __restrict__ wln_b,
    float* __restrict__ wts_out)
{
    __shared__ float xs_s[8][208];
    __shared__ float a_s[8][128];
    __shared__ float a2_s[8][128];
    __shared__ float g_s[8][416];

    const int tid = threadIdx.x;
    const int n0  = blockIdx.x * 8;

    for (int idx = tid; idx < 8 * V_DIM; idx += 128) {
        int r = idx / V_DIM, v = idx - r * V_DIM;
        xs_s[r][v] = x[(n0 + r) * V_DIM + v];
    }
    __syncthreads();

    {
        float acc[8];
        #pragma unroll
        for (int r = 0; r < 8; r++) acc[r] = 0.0f;
        for (int k = 0; k < V_DIM; k++) {
            float w = wfc1_w[k * 128 + tid];
            #pragma unroll
            for (int r = 0; r < 8; r++) acc[r] = fmaf(xs_s[r][k], w, acc[r]);
        }
        float b = wfc1_b[tid];
        #pragma unroll
        for (int r = 0; r < 8; r++) a_s[r][tid] = eluf_(acc[r] + b);
    }
    __syncthreads();

    {
        float acc[8];
        #pragma unroll
        for (int r = 0; r < 8; r++) acc[r] = 0.0f;
        for (int k = 0; k < 128; k++) {
            float w = wfc2_w[k * 128 + tid];
            #pragma unroll
            for (int r = 0; r < 8; r++) acc[r] = fmaf(a_s[r][k], w, acc[r]);
        }
        float b = wfc2_b[tid];
        #pragma unroll
        for (int r = 0; r < 8; r++) a2_s[r][tid] = acc[r] + b;
    }
    __syncthreads();

    for (int jj = tid; jj < 2 * V_DIM; jj += 128) {
        float acc[8];
        #pragma unroll
        for (int r = 0; r < 8; r++) acc[r] = 0.0f;
        for (int k = 0; k < 128; k++) {
            float w = wglu_w[k * (2 * V_DIM) + jj];
            #pragma unroll
            for (int r = 0; r < 8; r++) acc[r] = fmaf(a2_s[r][k], w, acc[r]);
        }
        float b = wglu_b[jj];
        #pragma unroll
        for (int r = 0; r < 8; r++) g_s[r][jj] = acc[r] + b;
    }
    __syncthreads();

    const int warp = tid >> 5, lane = tid & 31;
    for (int r = warp * 2; r < warp * 2 + 2; r++) {
        float s1 = 0.0f, s2 = 0.0f;
        for (int v = lane; v < V_DIM; v += 32) {
            float z = xs_s[r][v] + g_s[r][v] * sigmoidf_(g_s[r][V_DIM + v]);
            g_s[r][v] = z;
            s1 += z; s2 += z * z;
        }
        #pragma unroll
        for (int m = 16; m; m >>= 1) {
            s1 += __shfl_xor_sync(0xffffffffu, s1, m);
            s2 += __shfl_xor_sync(0xffffffffu, s2, m);
        }
        float mu  = s1 * (1.0f / (float)V_DIM);
        float var = s2 * (1.0f / (float)V_DIM) - mu * mu;
        float rs  = rsqrtf(var + 1e-5f);

        float mx = -3.4e38f;
        for (int v = lane; v < V_DIM; v += 32) {
            float y = fmaf((g_s[r][v] - mu) * rs, wln_g[v], wln_b[v]);
            g_s[r][v] = y;
            mx = fmaxf(mx, y);
        }
        #pragma unroll
        for (int m = 16; m; m >>= 1) mx = fmaxf(mx, __shfl_xor_sync(0xffffffffu, mx, m));

        float se = 0.0f;
        for (int v = lane; v < V_DIM; v += 32) {
            float e = expf(g_s[r][v] - mx);
            g_s[r][v] = e;
            se += e;
        }
        #pragma unroll
        for (int m = 16; m; m >>= 1) se += __shfl_xor_sync(0xffffffffu, se, m);
        float inv = 1.0f / se;
        for (int v = lane; v < V_DIM; v += 32)
            wts_out[(n0 + r) * V_DIM + v] = g_s[r][v] * inv;
    }
}

// ---------------------------------------------------------------------------
// GEMM helpers (unchanged)
// ---------------------------------------------------------------------------
__device__ __forceinline__ void gemm_128(float c[8][8], const float* __restrict__ aT,
                                         const float* __restrict__ bS, int tx, int ty)
{
    #pragma unroll 2
    for (int k = 0; k < 128; k++) {
        float4 a0 = *(const float4*)(aT + k * 128 + ty * 8);
        float4 a1 = *(const float4*)(aT + k * 128 + ty * 8 + 4);
        float4 b0 = *(const float4*)(bS + k * 128 + tx * 8);
        float4 b1 = *(const float4*)(bS + k * 128 + tx * 8 + 4);
        float av[8] = {a0.x, a0.y, a0.z, a0.w, a1.x, a1.y, a1.z, a1.w};
        float bv[8] = {b0.x, b0.y, b0.z, b0.w, b1.x, b1.y, b1.z, b1.w};
        #pragma unroll
        for (int i = 0; i < 8; i++)
            #pragma unroll
            for (int j = 0; j < 8; j++)
                c[i][j] = fmaf(av[i], bv[j], c[i][j]);
    }
}

__device__ __forceinline__ void load_gluT(float* __restrict__ wS,
                                          const float* __restrict__ gbase, int tid)
{
    #pragma unroll
    for (int r = 0; r < 16; r++) {
        int m  = tid + 256 * r;
        int g  = m & 127;
        int kq = m >> 7;
        float4 val = *(const float4*)(gbase + g * 128 + kq * 4);
        wS[(kq * 4 + 0) * 128 + g] = val.x;
        wS[(kq * 4 + 1) * 128 + g] = val.y;
        wS[(kq * 4 + 2) * 128 + g] = val.z;
        wS[(kq * 4 + 3) * 128 + g] = val.w;
    }
}

// ---------------------------------------------------------------------------
// Kernel T: build the table. One CTA per (v, 128-node tile).
// Identical math to the old kV body, with "rows" = interpolation nodes.
// ---------------------------------------------------------------------------
__global__ __launch_bounds__(256, 1) void kT(
    const float* __restrict__ fc1_w,  const float* __restrict__ fc1_b,
    const float* __restrict__ fc2_w,  const float* __restrict__ fc2_b,
    const float* __restrict__ glu_w,  const float* __restrict__ glu_b,
    const float* __restrict__ skip_w, const float* __restrict__ skip_b,
    const float* __restrict__ ln_g,   const float* __restrict__ ln_b)
{
    extern __shared__ float sm[];
    float* hT  = sm;            // 128x128
    float* wS  = sm + 16384;    // 128x128
    float* gaS = sm + 32768;    // 128x128
    __shared__ float x_s[128], w1_s[128], b1_s[128], skw_s[128], skb_s[128];

    const int tid = threadIdx.x;
    const int tx  = tid & 15;
    const int ty  = tid >> 4;
    const int v   = blockIdx.x;
    const int j0  = blockIdx.y * 128;
    const float dx = (XMAX - XMIN) / (float)(J_NODES - 1);

    float lng[8], lnb[8];
    #pragma unroll
    for (int j = 0; j < 8; j++) { lng[j] = ln_g[tx * 8 + j]; lnb[j] = ln_b[tx * 8 + j]; }

    if (tid < 128) {
        x_s[tid]   = XMIN + (float)(j0 + tid) * dx;
        w1_s[tid]  = fc1_w[v * H_DIM + tid];
        b1_s[tid]  = fc1_b[v * H_DIM + tid];
        skw_s[tid] = skip_w[v * H_DIM + tid];
        skb_s[tid] = skip_b[v * H_DIM + tid];
    }
    {   // stage fc2_w[v]
        const float4* src = (const float4*)(fc2_w + (size_t)v * 16384);
        float4* dst = (float4*)wS;
        #pragma unroll
        for (int i = 0; i < 16; i++) dst[tid + 256 * i] = src[tid + 256 * i];
    }
    __syncthreads();

    // h (transposed)
    #pragma unroll
    for (int i = 0; i < 8; i++) {
        float xi = x_s[ty * 8 + i];
        #pragma unroll
        for (int j = 0; j < 8; j++) {
            int jj = tx * 8 + j;
            float z = fmaf(xi, w1_s[jj], b1_s[jj]);
            hT[jj * 128 + ty * 8 + i] = (z > 0.0f) ? z : expm1f(z);
        }
    }
    __syncthreads();

    float c[8][8];
    #pragma unroll
    for (int i = 0; i < 8; i++)
        #pragma unroll
        for (int j = 0; j < 8; j++) c[i][j] = 0.0f;
    gemm_128(c, hT, wS, tx, ty);                 // h2 = h @ fc2_w[v]
    __syncthreads();

    #pragma unroll
    for (int j = 0; j < 8; j++) {
        int jj = tx * 8 + j;
        float b = fc2_b[v * 128 + jj];
        #pragma unroll
        for (int i = 0; i < 8; i++)
            hT[jj * 128 + ty * 8 + i] = c[i][j] + b;
    }
    load_gluT(wS, glu_w + (size_t)v * 32768, tid);
    __syncthreads();

    #pragma unroll
    for (int i = 0; i < 8; i++)
        #pragma unroll
        for (int j = 0; j < 8; j++) c[i][j] = 0.0f;
    gemm_128(c, hT, wS, tx, ty);                 // fc_out half
    #pragma unroll
    for (int i = 0; i < 8; i++)
        #pragma unroll
        for (int j = 0; j < 8; j++)
            gaS[(ty * 8 + i) * 128 + tx * 8 + j] = c[i][j] + glu_b[v * 256 + tx * 8 + j];
    __syncthreads();

    load_gluT(wS, glu_w + (size_t)v * 32768 + 16384, tid);
    __syncthreads();

    #pragma unroll
    for (int i = 0; i < 8; i++)
        #pragma unroll
        for (int j = 0; j < 8; j++) c[i][j] = 0.0f;
    gemm_128(c, hT, wS, tx, ty);                 // gate half

    float gbb[8];
    #pragma unroll
    for (int j = 0; j < 8; j++) gbb[j] = glu_b[v * 256 + 128 + tx * 8 + j];

    float* trow = g_tab + ((size_t)v * J_NODES + j0) * H_DIM;

    #pragma unroll
    for (int i = 0; i < 8; i++) {
        int nl = ty * 8 + i;
        float xi = x_s[nl];
        float s1 = 0.0f, s2 = 0.0f;
        #pragma unroll
        for (int j = 0; j < 8; j++) {
            int jj = tx * 8 + j;
            float gb  = c[i][j] + gbb[j];
            float val = gaS[nl * 128 + jj] * sigmoidf_(gb)
                      + fmaf(xi, skw_s[jj], skb_s[jj]);
            gaS[nl * 128 + jj] = val;
            s1 += val; s2 += val * val;
        }
        #pragma unroll
        for (int m = 8; m; m >>= 1) {
            s1 += __shfl_xor_sync(0xffffffffu, s1, m);
            s2 += __shfl_xor_sync(0xffffffffu, s2, m);
        }
        float mu = s1 * (1.0f / 128.0f);
        float rs = rsqrtf(s2 * (1.0f / 128.0f) - mu * mu + 1e-5f);
        float y[8];
        #pragma unroll
        for (int j = 0; j < 8; j++) {
            float vn = (gaS[nl * 128 + tx * 8 + j] - mu) * rs;
            y[j] = fmaf(vn, lng[j], lnb[j]);
        }
        *(float4*)(trow + (size_t)nl * 128 + tx * 8)     = make_float4(y[0], y[1], y[2], y[3]);
        *(float4*)(trow + (size_t)nl * 128 + tx * 8 + 4) = make_float4(y[4], y[5], y[6], y[7]);
    }
}

// ---------------------------------------------------------------------------
// Kernel I: cubic Lagrange interpolation + softmax-weighted accumulation.
// One warp per output row n. out[n,:] = sum_v sum_d wts[n,v]*c_d * T_v[j+d,:]
// ---------------------------------------------------------------------------
__global__ __launch_bounds__(256) void kI(
    const float* __restrict__ x,
    const float* __restrict__ wts,
    float* __restrict__ out)
{
    const int n    = blockIdx.x * 8 + (threadIdx.x >> 5);
    const int lane = threadIdx.x & 31;
    const float inv_dx = (float)(J_NODES - 1) / (XMAX - XMIN);
    const size_t base = (size_t)n * V_DIM;

    float4 acc = make_float4(0.0f, 0.0f, 0.0f, 0.0f);

    #pragma unroll 2
    for (int v = 0; v < V_DIM; v++) {
        float xv = __ldg(x + base + v);
        float wv = __ldg(wts + base + v);
        float t = (xv - XMIN) * inv_dx;
        int j = (int)t;
        j = max(1, min(j, J_NODES - 3));
        float f = t - (float)j;
        float fm1 = f - 1.0f, fm2 = f - 2.0f, fp1 = f + 1.0f;
        float c0 = wv * (-1.0f / 6.0f) * f * fm1 * fm2;
        float c1 = wv * 0.5f * fp1 * fm1 * fm2;
        float c2 = wv * (-0.5f) * fp1 * f * fm2;
        float c3 = wv * (1.0f / 6.0f) * fp1 * f * fm1;

        const float4* r = (const float4*)(g_tab + ((size_t)v * J_NODES + j - 1) * H_DIM) + lane;
        float4 t0 = __ldg(r);
        float4 t1 = __ldg(r + 32);
        float4 t2 = __ldg(r + 64);
        float4 t3 = __ldg(r + 96);

        acc.x = fmaf(c0, t0.x, fmaf(c1, t1.x, fmaf(c2, t2.x, fmaf(c3, t3.x, acc.x))));
        acc.y = fmaf(c0, t0.y, fmaf(c1, t1.y, fmaf(c2, t2.y, fmaf(c3, t3.y, acc.y))));
        acc.z = fmaf(c0, t0.z, fmaf(c1, t1.z, fmaf(c2, t2.z, fmaf(c3, t3.z, acc.z))));
        acc.w = fmaf(c0, t0.w, fmaf(c1, t1.w, fmaf(c2, t2.w, fmaf(c3, t3.w, acc.w))));
    }

    *(float4*)(out + (size_t)n * H_DIM + lane * 4) = acc;
}

// ---------------------------------------------------------------------------
extern "C" void kernel_launch(void* const* d_in, const int* in_sizes, int n_in,
                              void* d_out, int out_size)
{
    const float* x      = (const float*)d_in[0];
    const float* fc1_w  = (const float*)d_in[1];
    const float* fc1_b  = (const float*)d_in[2];
    const float* fc2_w  = (const float*)d_in[3];
    const float* fc2_b  = (const float*)d_in[4];
    const float* glu_w  = (const float*)d_in[5];
    const float* glu_b  = (const float*)d_in[6];
    const float* skip_w = (const float*)d_in[7];
    const float* skip_b = (const float*)d_in[8];
    const float* ln_g   = (const float*)d_in[9];
    const float* ln_b   = (const float*)d_in[10];
    const float* wfc1_w = (const float*)d_in[11];
    const float* wfc1_b = (const float*)d_in[12];
    const float* wfc2_w = (const float*)d_in[13];
    const float* wfc2_b = (const float*)d_in[14];
    const float* wglu_w = (const float*)d_in[15];
    const float* wglu_b = (const float*)d_in[16];
    const float* wln_g  = (const float*)d_in[17];
    const float* wln_b  = (const float*)d_in[18];

    float* out = (float*)d_out;
    float* wts = out + NH;   // tuple (out, wts): out first, then wts

    cudaFuncSetAttribute(kT, cudaFuncAttributeMaxDynamicSharedMemorySize, 196608);

    // table build first (independent of kW), then weights, then interpolation
    kT<<<dim3(V_DIM, J_NODES / 128), 256, 196608>>>(
        fc1_w, fc1_b, fc2_w, fc2_b, glu_w, glu_b,
        skip_w, skip_b, ln_g, ln_b);
    kW<<<N_ROWS / 8, 128>>>(x, wfc1_w, wfc1_b, wfc2_w, wfc2_b,
                            wglu_w, wglu_b, wln_g, wln_b, wts);
    kI<<<N_ROWS / 8, 256>>>(x, wts, out);
}